// round 6
// baseline (speedup 1.0000x reference)
#include <cuda_runtime.h>
#include <cstdint>

// ---------------------------------------------------------------------------
// MPS amplitude contraction, segment-table approach (v6).
// amplitude(s) = left[x0] . B[x1] ... B[x62] . right[x63]   (complex, D=16)
//
// Split: Lvec covers x0..x13 (14 bits), 6 x Seg6 cover x14..x49 (36 bits),
//        Rvec covers x50..x63 (14 bits).
// v6: 3-launch pipeline.
//   kA (64 blocks): per block c, build Seg3 pair from B via smem matmuls,
//       emit Seg6[c], Lv8[(a2<<6)|c], Rv8[(c<<2)|b2].
//   kB (128 blocks): k4 table expansion (Lvec/Rvec) + fused spin-bit pack.
//   k_main (148 blocks x 448 thr): per-sample Lvec gather + 6 smem matvecs
//       (lane-rotated LDS.128, fma.rn.f32x2) + Rvec dot.
// ---------------------------------------------------------------------------

typedef unsigned long long ull;

__device__ float2 g_seg [64 * 256];
__device__ float2 g_lv8 [256 * 16];
__device__ float2 g_rv8 [256 * 16];
__device__ float2 g_lvec[16384 * 16];
__device__ float2 g_rvec[16384 * 16];
__device__ ull    g_xpack[131072];

// ---- packed fp32x2 helpers ----
__device__ __forceinline__ ull pack2(float lo, float hi) {
    ull r; asm("mov.b64 %0, {%1,%2};" : "=l"(r) : "f"(lo), "f"(hi)); return r;
}
__device__ __forceinline__ void unpack2(ull v, float& lo, float& hi) {
    asm("mov.b64 {%0,%1}, %2;" : "=f"(lo), "=f"(hi) : "l"(v));
}
__device__ __forceinline__ ull ffma2(ull a, ull b, ull c) {
    ull d; asm("fma.rn.f32x2 %0, %1, %2, %3;" : "=l"(d) : "l"(a), "l"(b), "l"(c));
    return d;
}
__device__ __forceinline__ void lds128(unsigned addr, ull& p0, ull& p1) {
    asm volatile("ld.shared.v2.b64 {%0,%1}, [%2];" : "=l"(p0), "=l"(p1) : "r"(addr));
}
__device__ __forceinline__ void ldg128(const void* p, ull& p0, ull& p1) {
    asm volatile("ld.global.nc.v2.b64 {%0,%1}, [%2];" : "=l"(p0), "=l"(p1) : "l"(p));
}

// scalar complex fma: (rr,ri) += (ax+i ay) * (bx+i by)
__device__ __forceinline__ void cfma(float& rr, float& ri, float ax, float ay,
                                     float bx, float by) {
    rr = fmaf(ax, bx, rr);
    rr = fmaf(-ay, by, rr);
    ri = fmaf(ax, by, ri);
    ri = fmaf(ay, bx, ri);
}

// 16x16 complex matmul, one output element per thread (e = i*16+k, 256 thr)
__device__ __forceinline__ void mm16(const float2* A, const float2* Bm,
                                     float2* C, int e) {
    int i = e >> 4, k = e & 15;
    float xr = 0.f, xi = 0.f;
#pragma unroll
    for (int j = 0; j < 16; j++) {
        float2 a = A[(i << 4) + j], b = Bm[(j << 4) + k];
        cfma(xr, xi, a.x, a.y, b.x, b.y);
    }
    C[e] = make_float2(xr, xi);
}

// ---------------------------------------------------------------------------
// kA: 64 blocks x 256 threads. Block c builds Seg6[c] from raw B matrices
// (5 smem matmuls), plus Lv2/Rv2 (redundant, tiny) -> Lv8 / Rv8 slices.
// ---------------------------------------------------------------------------
__global__ void kA(const float* __restrict__ br_, const float* __restrict__ bi_,
                   const float* __restrict__ lr_, const float* __restrict__ li_,
                   const float* __restrict__ rr_, const float* __restrict__ ri_) {
    __shared__ float2 sB[512], sT[256], sA3[256], sB3[256], sS6[256];
    __shared__ float2 sLv2[64], sRv2[64];
    __shared__ float sLr[32], sLi[32], sRr[32], sRi[32];
    int e = threadIdx.x, c = blockIdx.x;

    sB[e]       = make_float2(br_[e],       bi_[e]);
    sB[e + 256] = make_float2(br_[e + 256], bi_[e + 256]);
    if (e < 32) { sLr[e] = lr_[e]; sLi[e] = li_[e]; sRr[e] = rr_[e]; sRi[e] = ri_[e]; }
    __syncthreads();

    int a = c >> 3, b = c & 7;
    // Seg3[a] = B[a2].B[a1].B[a0]  (MSB-first)
    mm16(sB + (((a >> 1) & 1) << 8), sB + ((a & 1) << 8), sT, e);  __syncthreads();
    mm16(sB + ((a >> 2) << 8), sT, sA3, e);                        __syncthreads();
    mm16(sB + (((b >> 1) & 1) << 8), sB + ((b & 1) << 8), sT, e);  __syncthreads();
    mm16(sB + ((b >> 2) << 8), sT, sB3, e);                        __syncthreads();
    mm16(sA3, sB3, sS6, e);                                        __syncthreads();

    g_seg[(c << 8) + e] = sS6[e];

    // Lv2[(s<<1)|bb][k] = sum_j left[s][j] * B[bb][j][k]
    if (e < 64) {
        int v = e >> 4, k = e & 15, s = v >> 1, bb = v & 1;
        float xr = 0.f, xi = 0.f;
#pragma unroll
        for (int j = 0; j < 16; j++) {
            float2 m = sB[(bb << 8) + (j << 4) + k];
            cfma(xr, xi, sLr[s * 16 + j], sLi[s * 16 + j], m.x, m.y);
        }
        sLv2[e] = make_float2(xr, xi);
    } else if (e < 128) {
        // Rv2[(bb<<1)|r][i] = sum_j B[bb][i][j] * right[r][j]
        int t2 = e - 64, v = t2 >> 4, i = t2 & 15, bb = v >> 1, r = v & 1;
        float xr = 0.f, xi = 0.f;
#pragma unroll
        for (int j = 0; j < 16; j++) {
            float2 m = sB[(bb << 8) + (i << 4) + j];
            cfma(xr, xi, m.x, m.y, sRr[r * 16 + j], sRi[r * 16 + j]);
        }
        sRv2[t2] = make_float2(xr, xi);
    }
    __syncthreads();

    if (e < 64) {
        // Lv8[(a2<<6)|c][k] = sum_j Lv2[a2][j] * Seg6[c][j][k]
        int a2 = e >> 4, k = e & 15;
        float xr = 0.f, xi = 0.f;
#pragma unroll
        for (int j = 0; j < 16; j++) {
            float2 o = sLv2[(a2 << 4) + j];
            float2 m = sS6[(j << 4) + k];
            cfma(xr, xi, o.x, o.y, m.x, m.y);
        }
        g_lv8[(((a2 << 6) | c) << 4) + k] = make_float2(xr, xi);
    } else if (e < 128) {
        // Rv8[(c<<2)|b2][i] = sum_j Seg6[c][i][j] * Rv2[b2][j]
        int t2 = e - 64, b2 = t2 >> 4, i = t2 & 15;
        float xr = 0.f, xi = 0.f;
#pragma unroll
        for (int j = 0; j < 16; j++) {
            float2 m = sS6[(i << 4) + j];
            float2 w = sRv2[(b2 << 4) + j];
            cfma(xr, xi, m.x, m.y, w.x, w.y);
        }
        g_rv8[(((c << 2) | b2) << 4) + i] = make_float2(xr, xi);
    }
}

// ---------------------------------------------------------------------------
// kB: 128 blocks x 256 threads.  Table expansion (k4) + fused bit-pack.
// Blocks 0..63:  Lvec[(a8<<6)|c] = Lv8[a8].Seg6[c]
// Blocks 64..127: Rvec[(c<<8)|b8] = Seg6[c].Rv8[b8]
// All blocks: warp W packs samples [128W, 128W+128).
// ---------------------------------------------------------------------------
__global__ void kB(const int* __restrict__ x, int N) {
    __shared__ float2 S[256];
    int blk = blockIdx.x;
    int t = threadIdx.x;

    if (blk < 64) {
        int c = blk;
        S[t] = g_seg[(c << 8) + t];           // S[j*16+k] = Seg6[c][j][k]
        __syncthreads();
        int k = t & 15, a8l = t >> 4;
#pragma unroll 1
        for (int p = 0; p < 16; p++) {
            int a8 = (p << 4) | a8l;
            const float2* w = g_lv8 + (a8 << 4);
            float xr = 0.f, xi = 0.f;
#pragma unroll
            for (int j = 0; j < 16; j++) {
                float2 o = __ldg(&w[j]);       // warp-broadcast
                float2 bb = S[(j << 4) + k];
                cfma(xr, xi, o.x, o.y, bb.x, bb.y);
            }
            g_lvec[(((a8 << 6) | c) << 4) + k] = make_float2(xr, xi);
        }
    } else {
        int c = blk - 64;
        {
            int i = t >> 4, j = t & 15;
            S[(j << 4) | i] = g_seg[(c << 8) + t];  // transposed stage
        }
        __syncthreads();
        int il = t & 15, b8l = t >> 4;
#pragma unroll 1
        for (int p = 0; p < 16; p++) {
            int b8 = (p << 4) | b8l;
            const float2* w = g_rv8 + (b8 << 4);
            float xr = 0.f, xi = 0.f;
#pragma unroll
            for (int j = 0; j < 16; j++) {
                float2 ww = __ldg(&w[j]);      // warp-broadcast
                float2 bb = S[(j << 4) + il];  // Seg6[c][il][j]
                cfma(xr, xi, bb.x, bb.y, ww.x, ww.y);
            }
            g_rvec[(((c << 8) | b8) << 4) + il] = make_float2(xr, xi);
        }
    }

    // ---- fused pack: 1024 warps x 128 samples. packed bit (63-t) = x_t ----
    int W = (blk << 3) + (t >> 5);
    int lane = t & 31;
#pragma unroll 1
    for (int g = 0; g < 4; g++) {
        int s0 = (W << 7) + (g << 5);
        if (s0 >= N) break;
        ull mine = 0;
#pragma unroll 1
        for (int q = 0; q < 32; q++) {
            size_t base = (size_t)(s0 + q) << 6;
            unsigned b0 = __ballot_sync(0xFFFFFFFFu, x[base + lane] & 1);
            unsigned b1 = __ballot_sync(0xFFFFFFFFu, x[base + 32 + lane] & 1);
            ull packed = ((ull)__brev(b0) << 32) | (ull)__brev(b1);
            if (lane == q) mine = packed;
        }
        g_xpack[s0 + lane] = mine;
    }
}

// ---------------------------------------------------------------------------
// Main kernel. One thread per sample, balanced contiguous chunk per block.
// Table (128 KB) in smem, plain layout; column pairs read in lane-rotated
// order (deterministic 4-phase LDS.128, idx-independent). Register pair u
// of the state holds logical pair (u+rot)&7 after the first matvec.
// blockDim 448: chunk 886 = 448+438 -> ~99% lane utilization, reg cap 146.
// ---------------------------------------------------------------------------
__global__ __launch_bounds__(448) void k_main(float* __restrict__ out, int N) {
    extern __shared__ float2 sSeg[];  // 64 * 256 float2 = 128 KB

    {
        const float4* src = reinterpret_cast<const float4*>(g_seg);
        float4* dst = reinterpret_cast<float4*>(sSeg);
        for (int e = threadIdx.x; e < 64 * 128; e += blockDim.x) dst[e] = src[e];
    }
    __syncthreads();

    unsigned sb;
    asm("{ .reg .u64 t; cvta.to.shared.u64 t, %1; cvt.u32.u64 %0, t; }"
        : "=r"(sb) : "l"(sSeg));
    const unsigned rot    = threadIdx.x & 7u;
    const unsigned rot16  = rot << 4;
    const unsigned rot256 = rot << 8;

    int chunk = (N + gridDim.x - 1) / gridDim.x;
    int start = blockIdx.x * chunk;
    int end = min(start + chunk, N);

    for (int s = start + (int)threadIdx.x; s < end; s += (int)blockDim.x) {
        ull packed = __ldg(&g_xpack[s]);
        unsigned idxl = (unsigned)(packed >> 50);         // x0..x13
        unsigned idxr = (unsigned)packed & 0x3FFFu;       // x50..x63
        ull sp = packed << 14;                            // x14 at bit 63

        // ---- start vector: Lvec[idxl], logical register order ----
        float mr[16], mi[16];
        {
            const char* lb = (const char*)g_lvec + ((size_t)idxl << 7);
#pragma unroll
            for (int u = 0; u < 8; u++) {
                ull a, b;
                ldg128(lb + (u << 4), a, b);
                unpack2(a, mr[2 * u],     mi[2 * u]);
                unpack2(b, mr[2 * u + 1], mi[2 * u + 1]);
            }
        }

        // ---- matvec 1: rows addressed by immediate offsets ----
        {
            unsigned idx = (unsigned)(sp >> 58);
            sp <<= 6;
            unsigned mb = sb + (idx << 11);
            ull P[16], Q[16];
#pragma unroll
            for (int e = 0; e < 16; e++) { P[e] = 0ull; Q[e] = 0ull; }
            unsigned pu[8];
#pragma unroll
            for (int u = 0; u < 8; u++) pu[u] = mb + ((rot16 + (u << 4)) & 127u);
#pragma unroll
            for (int i = 0; i < 16; i++) {
                float ar = mr[i], ai = mi[i];
                ull arr = pack2(ar, ar), ai2 = pack2(ai, -ai);
#pragma unroll
                for (int u = 0; u < 8; u++) {
                    ull b0, b1;
                    lds128(pu[u] + (unsigned)(i << 7), b0, b1);
                    P[2 * u]     = ffma2(arr, b0, P[2 * u]);
                    Q[2 * u]     = ffma2(ai2, b0, Q[2 * u]);
                    P[2 * u + 1] = ffma2(arr, b1, P[2 * u + 1]);
                    Q[2 * u + 1] = ffma2(ai2, b1, Q[2 * u + 1]);
                }
            }
#pragma unroll
            for (int e = 0; e < 16; e++) {
                float pl, ph, ql, qh;
                unpack2(P[e], pl, ph);
                unpack2(Q[e], ql, qh);
                mr[e] = pl + qh;   // nr = ar*bx - ai*by
                mi[e] = ph + ql;   // ni = ar*by + ai*bx
            }
        }

        // ---- matvecs 2..6: state pair u holds logical pair (u+rot)&7 ----
#pragma unroll 1
        for (int kseg = 1; kseg < 6; kseg++) {
            unsigned idx = (unsigned)(sp >> 58);
            sp <<= 6;
            unsigned mb = sb + (idx << 11);
            ull P[16], Q[16];
#pragma unroll
            for (int e = 0; e < 16; e++) { P[e] = 0ull; Q[e] = 0ull; }
            unsigned pu[8];
#pragma unroll
            for (int u = 0; u < 8; u++) pu[u] = mb + ((rot16 + (u << 4)) & 127u);
#pragma unroll
            for (int spn = 0; spn < 8; spn++) {
                unsigned row = (rot256 + (unsigned)(spn << 8)) & 2047u;
#pragma unroll
                for (int hf = 0; hf < 2; hf++) {
                    float ar = mr[2 * spn + hf], ai = mi[2 * spn + hf];
                    ull arr = pack2(ar, ar), ai2 = pack2(ai, -ai);
#pragma unroll
                    for (int u = 0; u < 8; u++) {
                        ull b0, b1;
                        lds128(pu[u] + row + (unsigned)(hf << 7), b0, b1);
                        P[2 * u]     = ffma2(arr, b0, P[2 * u]);
                        Q[2 * u]     = ffma2(ai2, b0, Q[2 * u]);
                        P[2 * u + 1] = ffma2(arr, b1, P[2 * u + 1]);
                        Q[2 * u + 1] = ffma2(ai2, b1, Q[2 * u + 1]);
                    }
                }
            }
#pragma unroll
            for (int e = 0; e < 16; e++) {
                float pl, ph, ql, qh;
                unpack2(P[e], pl, ph);
                unpack2(Q[e], ql, qh);
                mr[e] = pl + qh;
                mi[e] = ph + ql;
            }
        }

        // ---- final dot with Rvec[idxr], same pair rotation ----
        float accr = 0.f, acci = 0.f;
        {
            const char* rb = (const char*)g_rvec + ((size_t)idxr << 7);
#pragma unroll
            for (int u = 0; u < 8; u++) {
                ull a, b;
                ldg128(rb + ((rot16 + (u << 4)) & 127u), a, b);
                float c0x, c0y, c1x, c1y;
                unpack2(a, c0x, c0y);
                unpack2(b, c1x, c1y);
                int e0 = 2 * u, e1 = 2 * u + 1;
                accr = fmaf(mr[e0], c0x, accr);  accr = fmaf(-mi[e0], c0y, accr);
                acci = fmaf(mr[e0], c0y, acci);  acci = fmaf(mi[e0], c0x, acci);
                accr = fmaf(mr[e1], c1x, accr);  accr = fmaf(-mi[e1], c1y, accr);
                acci = fmaf(mr[e1], c1y, acci);  acci = fmaf(mi[e1], c1x, acci);
            }
        }

        out[s]     = accr;
        out[N + s] = acci;
    }
}

// ---------------------------------------------------------------------------
// kernel_launch
// inputs (metadata order): x, left_r, left_i, bulk_r, bulk_i, right_r, right_i
// out: float32, [2, N] flattened (re then im)
// ---------------------------------------------------------------------------
extern "C" void kernel_launch(void* const* d_in, const int* in_sizes, int n_in,
                              void* d_out, int out_size) {
    const int*   x       = (const int*)d_in[0];
    const float* left_r  = (const float*)d_in[1];
    const float* left_i  = (const float*)d_in[2];
    const float* bulk_r  = (const float*)d_in[3];
    const float* bulk_i  = (const float*)d_in[4];
    const float* right_r = (const float*)d_in[5];
    const float* right_i = (const float*)d_in[6];
    float* out = (float*)d_out;

    int N = in_sizes[0] / 64;

    static const size_t kSmem = 64 * 256 * sizeof(float2);  // 128 KB
    cudaFuncSetAttribute(k_main, cudaFuncAttributeMaxDynamicSharedMemorySize,
                         (int)kSmem);

    kA<<<64, 256>>>(bulk_r, bulk_i, left_r, left_i, right_r, right_i);
    kB<<<128, 256>>>(x, N);
    k_main<<<148, 448, kSmem>>>(out, N);
}

// round 7
// speedup vs baseline: 1.0280x; 1.0280x over previous
#include <cuda_runtime.h>
#include <cstdint>

// ---------------------------------------------------------------------------
// MPS amplitude contraction, segment-table approach (v7).
// amplitude(s) = left[x0] . B[x1] ... B[x62] . right[x63]   (complex, D=16)
//
// Split: Lvec covers x0..x13 (14 bits), 6 x Seg6 cover x14..x49 (36 bits),
//        Rvec covers x50..x63 (14 bits).
// v7: 3-launch pipeline, pack fused into k_main, dual-acc ILP in precompute.
//   kA (64 blocks): block c builds Seg6[c] from B via smem matmuls,
//       emits Seg6[c], Lv8[(a2<<6)|c], Rv8[(c<<2)|b2].
//   kB (128 blocks): table expansion Lvec/Rvec.
//   k_main (148 x 512): per-block bit-pack, then per-sample Lvec gather +
//       6 smem matvecs (lane-rotated LDS.128, fma.rn.f32x2) + Rvec dot.
// ---------------------------------------------------------------------------

typedef unsigned long long ull;

__device__ float2 g_seg [64 * 256];
__device__ float2 g_lv8 [256 * 16];
__device__ float2 g_rv8 [256 * 16];
__device__ float2 g_lvec[16384 * 16];
__device__ float2 g_rvec[16384 * 16];
__device__ ull    g_xpack[131072];

// ---- packed fp32x2 helpers ----
__device__ __forceinline__ ull pack2(float lo, float hi) {
    ull r; asm("mov.b64 %0, {%1,%2};" : "=l"(r) : "f"(lo), "f"(hi)); return r;
}
__device__ __forceinline__ void unpack2(ull v, float& lo, float& hi) {
    asm("mov.b64 {%0,%1}, %2;" : "=f"(lo), "=f"(hi) : "l"(v));
}
__device__ __forceinline__ ull ffma2(ull a, ull b, ull c) {
    ull d; asm("fma.rn.f32x2 %0, %1, %2, %3;" : "=l"(d) : "l"(a), "l"(b), "l"(c));
    return d;
}
__device__ __forceinline__ void lds128(unsigned addr, ull& p0, ull& p1) {
    asm volatile("ld.shared.v2.b64 {%0,%1}, [%2];" : "=l"(p0), "=l"(p1) : "r"(addr));
}
__device__ __forceinline__ void ldg128(const void* p, ull& p0, ull& p1) {
    asm volatile("ld.global.nc.v2.b64 {%0,%1}, [%2];" : "=l"(p0), "=l"(p1) : "l"(p));
}

// scalar complex fma: (rr,ri) += (ax+i ay) * (bx+i by)
__device__ __forceinline__ void cfma(float& rr, float& ri, float ax, float ay,
                                     float bx, float by) {
    rr = fmaf(ax, bx, rr);
    rr = fmaf(-ay, by, rr);
    ri = fmaf(ax, by, ri);
    ri = fmaf(ay, bx, ri);
}

// 16x16 complex matmul, one output element per thread (e = i*16+k, 256 thr),
// dual accumulator chains for ILP.
__device__ __forceinline__ void mm16(const float2* A, const float2* Bm,
                                     float2* C, int e) {
    int i = e >> 4, k = e & 15;
    float xr0 = 0.f, xi0 = 0.f, xr1 = 0.f, xi1 = 0.f;
#pragma unroll
    for (int j = 0; j < 16; j += 2) {
        float2 a0 = A[(i << 4) + j],     b0 = Bm[(j << 4) + k];
        float2 a1 = A[(i << 4) + j + 1], b1 = Bm[((j + 1) << 4) + k];
        cfma(xr0, xi0, a0.x, a0.y, b0.x, b0.y);
        cfma(xr1, xi1, a1.x, a1.y, b1.x, b1.y);
    }
    C[e] = make_float2(xr0 + xr1, xi0 + xi1);
}

// ---------------------------------------------------------------------------
// kA: 64 blocks x 256 threads. Block c builds Seg6[c] from raw B matrices
// (5 smem matmuls), plus Lv2/Rv2 (redundant, tiny) -> Lv8 / Rv8 slices.
// ---------------------------------------------------------------------------
__global__ void kA(const float* __restrict__ br_, const float* __restrict__ bi_,
                   const float* __restrict__ lr_, const float* __restrict__ li_,
                   const float* __restrict__ rr_, const float* __restrict__ ri_) {
    __shared__ float2 sB[512], sT[256], sA3[256], sB3[256], sS6[256];
    __shared__ float2 sLv2[64], sRv2[64];
    __shared__ float sLr[32], sLi[32], sRr[32], sRi[32];
    int e = threadIdx.x, c = blockIdx.x;

    sB[e]       = make_float2(br_[e],       bi_[e]);
    sB[e + 256] = make_float2(br_[e + 256], bi_[e + 256]);
    if (e < 32) { sLr[e] = lr_[e]; sLi[e] = li_[e]; sRr[e] = rr_[e]; sRi[e] = ri_[e]; }
    __syncthreads();

    int a = c >> 3, b = c & 7;
    mm16(sB + (((a >> 1) & 1) << 8), sB + ((a & 1) << 8), sT, e);  __syncthreads();
    mm16(sB + ((a >> 2) << 8), sT, sA3, e);                        __syncthreads();
    mm16(sB + (((b >> 1) & 1) << 8), sB + ((b & 1) << 8), sT, e);  __syncthreads();
    mm16(sB + ((b >> 2) << 8), sT, sB3, e);                        __syncthreads();
    mm16(sA3, sB3, sS6, e);                                        __syncthreads();

    g_seg[(c << 8) + e] = sS6[e];

    if (e < 64) {  // Lv2[(s<<1)|bb][k] = sum_j left[s][j] * B[bb][j][k]
        int v = e >> 4, k = e & 15, s = v >> 1, bb = v & 1;
        float xr = 0.f, xi = 0.f;
#pragma unroll
        for (int j = 0; j < 16; j++) {
            float2 m = sB[(bb << 8) + (j << 4) + k];
            cfma(xr, xi, sLr[s * 16 + j], sLi[s * 16 + j], m.x, m.y);
        }
        sLv2[e] = make_float2(xr, xi);
    } else if (e < 128) {  // Rv2[(bb<<1)|r][i] = sum_j B[bb][i][j] * right[r][j]
        int t2 = e - 64, v = t2 >> 4, i = t2 & 15, bb = v >> 1, r = v & 1;
        float xr = 0.f, xi = 0.f;
#pragma unroll
        for (int j = 0; j < 16; j++) {
            float2 m = sB[(bb << 8) + (i << 4) + j];
            cfma(xr, xi, m.x, m.y, sRr[r * 16 + j], sRi[r * 16 + j]);
        }
        sRv2[t2] = make_float2(xr, xi);
    }
    __syncthreads();

    if (e < 64) {  // Lv8[(a2<<6)|c][k] = sum_j Lv2[a2][j] * Seg6[c][j][k]
        int a2 = e >> 4, k = e & 15;
        float xr = 0.f, xi = 0.f;
#pragma unroll
        for (int j = 0; j < 16; j++) {
            float2 o = sLv2[(a2 << 4) + j];
            float2 m = sS6[(j << 4) + k];
            cfma(xr, xi, o.x, o.y, m.x, m.y);
        }
        g_lv8[(((a2 << 6) | c) << 4) + k] = make_float2(xr, xi);
    } else if (e < 128) {  // Rv8[(c<<2)|b2][i] = sum_j Seg6[c][i][j] * Rv2[b2][j]
        int t2 = e - 64, b2 = t2 >> 4, i = t2 & 15;
        float xr = 0.f, xi = 0.f;
#pragma unroll
        for (int j = 0; j < 16; j++) {
            float2 m = sS6[(i << 4) + j];
            float2 w = sRv2[(b2 << 4) + j];
            cfma(xr, xi, m.x, m.y, w.x, w.y);
        }
        g_rv8[(((c << 2) | b2) << 4) + i] = make_float2(xr, xi);
    }
}

// ---------------------------------------------------------------------------
// kB: 128 blocks x 256 threads. Table expansion with dual-acc ILP.
// Blocks 0..63:  Lvec[(a8<<6)|c] = Lv8[a8].Seg6[c]
// Blocks 64..127: Rvec[(c<<8)|b8] = Seg6[c].Rv8[b8]
// ---------------------------------------------------------------------------
__global__ void kB() {
    __shared__ float2 S[256];
    int blk = blockIdx.x;
    int t = threadIdx.x;

    if (blk < 64) {
        int c = blk;
        S[t] = g_seg[(c << 8) + t];           // S[j*16+k] = Seg6[c][j][k]
        __syncthreads();
        int k = t & 15, a8l = t >> 4;
#pragma unroll 1
        for (int p = 0; p < 16; p++) {
            int a8 = (p << 4) | a8l;
            const float2* w = g_lv8 + (a8 << 4);
            float xr0 = 0.f, xi0 = 0.f, xr1 = 0.f, xi1 = 0.f;
#pragma unroll
            for (int j = 0; j < 16; j += 2) {
                float2 o0 = __ldg(&w[j]),     b0 = S[(j << 4) + k];
                float2 o1 = __ldg(&w[j + 1]), b1 = S[((j + 1) << 4) + k];
                cfma(xr0, xi0, o0.x, o0.y, b0.x, b0.y);
                cfma(xr1, xi1, o1.x, o1.y, b1.x, b1.y);
            }
            g_lvec[(((a8 << 6) | c) << 4) + k] = make_float2(xr0 + xr1, xi0 + xi1);
        }
    } else {
        int c = blk - 64;
        {
            int i = t >> 4, j = t & 15;
            S[(j << 4) | i] = g_seg[(c << 8) + t];  // transposed stage
        }
        __syncthreads();
        int il = t & 15, b8l = t >> 4;
#pragma unroll 1
        for (int p = 0; p < 16; p++) {
            int b8 = (p << 4) | b8l;
            const float2* w = g_rv8 + (b8 << 4);
            float xr0 = 0.f, xi0 = 0.f, xr1 = 0.f, xi1 = 0.f;
#pragma unroll
            for (int j = 0; j < 16; j += 2) {
                float2 w0 = __ldg(&w[j]),     b0 = S[(j << 4) + il];
                float2 w1 = __ldg(&w[j + 1]), b1 = S[((j + 1) << 4) + il];
                cfma(xr0, xi0, b0.x, b0.y, w0.x, w0.y);
                cfma(xr1, xi1, b1.x, b1.y, w1.x, w1.y);
            }
            g_rvec[(((c << 8) | b8) << 4) + il] = make_float2(xr0 + xr1, xi0 + xi1);
        }
    }
}

// ---------------------------------------------------------------------------
// Main kernel. One thread per sample, balanced contiguous chunk per block.
// Fused per-block bit-pack (warp-ballot) overlapped with the 128 KB table
// smem load; single __syncthreads covers both. Column pairs read in
// lane-rotated order (deterministic 4-phase LDS.128). Register pair u of
// the state holds logical pair (u+rot)&7 after the first matvec.
// ---------------------------------------------------------------------------
__global__ __launch_bounds__(512) void k_main(const int* __restrict__ x,
                                              float* __restrict__ out, int N) {
    extern __shared__ float2 sSeg[];  // 64 * 256 float2 = 128 KB

    int chunk = (N + gridDim.x - 1) / gridDim.x;
    int start = blockIdx.x * chunk;
    int end = min(start + chunk, N);

    {
        const float4* src = reinterpret_cast<const float4*>(g_seg);
        float4* dst = reinterpret_cast<float4*>(sSeg);
        for (int e = threadIdx.x; e < 64 * 128; e += blockDim.x) dst[e] = src[e];
    }

    // ---- fused pack of this block's chunk: packed bit (63-t) = x_t ----
    {
        int wid = threadIdx.x >> 5, lane = threadIdx.x & 31;
        for (int s0 = start + (wid << 5); s0 < end; s0 += 512) {
            ull mine = 0;
#pragma unroll 1
            for (int q = 0; q < 32; q++) {
                int sidx = s0 + q;
                if (sidx >= end) break;  // uniform across warp
                size_t base = (size_t)sidx << 6;
                unsigned b0 = __ballot_sync(0xFFFFFFFFu, x[base + lane] & 1);
                unsigned b1 = __ballot_sync(0xFFFFFFFFu, x[base + 32 + lane] & 1);
                ull packed = ((ull)__brev(b0) << 32) | (ull)__brev(b1);
                if (lane == q) mine = packed;
            }
            if (s0 + lane < end) g_xpack[s0 + lane] = mine;
        }
    }
    __syncthreads();

    unsigned sb;
    asm("{ .reg .u64 t; cvta.to.shared.u64 t, %1; cvt.u32.u64 %0, t; }"
        : "=r"(sb) : "l"(sSeg));
    const unsigned rot    = threadIdx.x & 7u;
    const unsigned rot16  = rot << 4;
    const unsigned rot256 = rot << 8;

    for (int s = start + (int)threadIdx.x; s < end; s += (int)blockDim.x) {
        ull packed = g_xpack[s];
        unsigned idxl = (unsigned)(packed >> 50);         // x0..x13
        unsigned idxr = (unsigned)packed & 0x3FFFu;       // x50..x63
        ull sp = packed << 14;                            // x14 at bit 63

        // ---- start vector: Lvec[idxl], logical register order ----
        float mr[16], mi[16];
        {
            const char* lb = (const char*)g_lvec + ((size_t)idxl << 7);
#pragma unroll
            for (int u = 0; u < 8; u++) {
                ull a, b;
                ldg128(lb + (u << 4), a, b);
                unpack2(a, mr[2 * u],     mi[2 * u]);
                unpack2(b, mr[2 * u + 1], mi[2 * u + 1]);
            }
        }

        // ---- matvec 1: rows addressed by immediate offsets ----
        {
            unsigned idx = (unsigned)(sp >> 58);
            sp <<= 6;
            unsigned mb = sb + (idx << 11);
            ull P[16], Q[16];
#pragma unroll
            for (int e = 0; e < 16; e++) { P[e] = 0ull; Q[e] = 0ull; }
            unsigned pu[8];
#pragma unroll
            for (int u = 0; u < 8; u++) pu[u] = mb + ((rot16 + (u << 4)) & 127u);
#pragma unroll
            for (int i = 0; i < 16; i++) {
                float ar = mr[i], ai = mi[i];
                ull arr = pack2(ar, ar), ai2 = pack2(ai, -ai);
#pragma unroll
                for (int u = 0; u < 8; u++) {
                    ull b0, b1;
                    lds128(pu[u] + (unsigned)(i << 7), b0, b1);
                    P[2 * u]     = ffma2(arr, b0, P[2 * u]);
                    Q[2 * u]     = ffma2(ai2, b0, Q[2 * u]);
                    P[2 * u + 1] = ffma2(arr, b1, P[2 * u + 1]);
                    Q[2 * u + 1] = ffma2(ai2, b1, Q[2 * u + 1]);
                }
            }
#pragma unroll
            for (int e = 0; e < 16; e++) {
                float pl, ph, ql, qh;
                unpack2(P[e], pl, ph);
                unpack2(Q[e], ql, qh);
                mr[e] = pl + qh;   // nr = ar*bx - ai*by
                mi[e] = ph + ql;   // ni = ar*by + ai*bx
            }
        }

        // ---- matvecs 2..6: state pair u holds logical pair (u+rot)&7 ----
#pragma unroll 1
        for (int kseg = 1; kseg < 6; kseg++) {
            unsigned idx = (unsigned)(sp >> 58);
            sp <<= 6;
            unsigned mb = sb + (idx << 11);
            ull P[16], Q[16];
#pragma unroll
            for (int e = 0; e < 16; e++) { P[e] = 0ull; Q[e] = 0ull; }
            unsigned pu[8];
#pragma unroll
            for (int u = 0; u < 8; u++) pu[u] = mb + ((rot16 + (u << 4)) & 127u);
#pragma unroll
            for (int spn = 0; spn < 8; spn++) {
                unsigned row = (rot256 + (unsigned)(spn << 8)) & 2047u;
#pragma unroll
                for (int hf = 0; hf < 2; hf++) {
                    float ar = mr[2 * spn + hf], ai = mi[2 * spn + hf];
                    ull arr = pack2(ar, ar), ai2 = pack2(ai, -ai);
#pragma unroll
                    for (int u = 0; u < 8; u++) {
                        ull b0, b1;
                        lds128(pu[u] + row + (unsigned)(hf << 7), b0, b1);
                        P[2 * u]     = ffma2(arr, b0, P[2 * u]);
                        Q[2 * u]     = ffma2(ai2, b0, Q[2 * u]);
                        P[2 * u + 1] = ffma2(arr, b1, P[2 * u + 1]);
                        Q[2 * u + 1] = ffma2(ai2, b1, Q[2 * u + 1]);
                    }
                }
            }
#pragma unroll
            for (int e = 0; e < 16; e++) {
                float pl, ph, ql, qh;
                unpack2(P[e], pl, ph);
                unpack2(Q[e], ql, qh);
                mr[e] = pl + qh;
                mi[e] = ph + ql;
            }
        }

        // ---- final dot with Rvec[idxr], same pair rotation ----
        float accr = 0.f, acci = 0.f;
        {
            const char* rb = (const char*)g_rvec + ((size_t)idxr << 7);
#pragma unroll
            for (int u = 0; u < 8; u++) {
                ull a, b;
                ldg128(rb + ((rot16 + (u << 4)) & 127u), a, b);
                float c0x, c0y, c1x, c1y;
                unpack2(a, c0x, c0y);
                unpack2(b, c1x, c1y);
                int e0 = 2 * u, e1 = 2 * u + 1;
                accr = fmaf(mr[e0], c0x, accr);  accr = fmaf(-mi[e0], c0y, accr);
                acci = fmaf(mr[e0], c0y, acci);  acci = fmaf(mi[e0], c0x, acci);
                accr = fmaf(mr[e1], c1x, accr);  accr = fmaf(-mi[e1], c1y, accr);
                acci = fmaf(mr[e1], c1y, acci);  acci = fmaf(mi[e1], c1x, acci);
            }
        }

        out[s]     = accr;
        out[N + s] = acci;
    }
}

// ---------------------------------------------------------------------------
// kernel_launch
// inputs (metadata order): x, left_r, left_i, bulk_r, bulk_i, right_r, right_i
// out: float32, [2, N] flattened (re then im)
// ---------------------------------------------------------------------------
extern "C" void kernel_launch(void* const* d_in, const int* in_sizes, int n_in,
                              void* d_out, int out_size) {
    const int*   x       = (const int*)d_in[0];
    const float* left_r  = (const float*)d_in[1];
    const float* left_i  = (const float*)d_in[2];
    const float* bulk_r  = (const float*)d_in[3];
    const float* bulk_i  = (const float*)d_in[4];
    const float* right_r = (const float*)d_in[5];
    const float* right_i = (const float*)d_in[6];
    float* out = (float*)d_out;

    int N = in_sizes[0] / 64;

    static const size_t kSmem = 64 * 256 * sizeof(float2);  // 128 KB
    cudaFuncSetAttribute(k_main, cudaFuncAttributeMaxDynamicSharedMemorySize,
                         (int)kSmem);

    kA<<<64, 256>>>(bulk_r, bulk_i, left_r, left_i, right_r, right_i);
    kB<<<128, 256>>>();
    k_main<<<148, 512, kSmem>>>(x, out, N);
}

// round 8
// speedup vs baseline: 1.2273x; 1.1938x over previous
#include <cuda_runtime.h>
#include <cstdint>

// ---------------------------------------------------------------------------
// MPS amplitude contraction, segment-table approach (v8).
// amplitude(s) = left[x0] . B[x1] ... B[x62] . right[x63]   (complex, D=16)
//
// Split: Lvec covers x0..x13 (14 bits), 6 x Seg6 cover x14..x49 (36 bits),
//        Rvec covers x50..x63 (14 bits).
// v8: standalone MLP-unrolled pack kernel; k_main = proven R5 hot loop;
//     two no-op launches so ncu (-s 5 -c 1) profiles k_main.
// ---------------------------------------------------------------------------

typedef unsigned long long ull;

__device__ float2 g_seg [64 * 256];
__device__ float2 g_lv8 [256 * 16];
__device__ float2 g_rv8 [256 * 16];
__device__ float2 g_lvec[16384 * 16];
__device__ float2 g_rvec[16384 * 16];
__device__ ull    g_xpack[131072];

// ---- packed fp32x2 helpers ----
__device__ __forceinline__ ull pack2(float lo, float hi) {
    ull r; asm("mov.b64 %0, {%1,%2};" : "=l"(r) : "f"(lo), "f"(hi)); return r;
}
__device__ __forceinline__ void unpack2(ull v, float& lo, float& hi) {
    asm("mov.b64 {%0,%1}, %2;" : "=f"(lo), "=f"(hi) : "l"(v));
}
__device__ __forceinline__ ull ffma2(ull a, ull b, ull c) {
    ull d; asm("fma.rn.f32x2 %0, %1, %2, %3;" : "=l"(d) : "l"(a), "l"(b), "l"(c));
    return d;
}
__device__ __forceinline__ void lds128(unsigned addr, ull& p0, ull& p1) {
    asm volatile("ld.shared.v2.b64 {%0,%1}, [%2];" : "=l"(p0), "=l"(p1) : "r"(addr));
}
__device__ __forceinline__ void ldg128(const void* p, ull& p0, ull& p1) {
    asm volatile("ld.global.nc.v2.b64 {%0,%1}, [%2];" : "=l"(p0), "=l"(p1) : "l"(p));
}

// scalar complex fma: (rr,ri) += (ax+i ay) * (bx+i by)
__device__ __forceinline__ void cfma(float& rr, float& ri, float ax, float ay,
                                     float bx, float by) {
    rr = fmaf(ax, bx, rr);
    rr = fmaf(-ay, by, rr);
    ri = fmaf(ax, by, ri);
    ri = fmaf(ay, bx, ri);
}

// 16x16 complex matmul, one output element per thread (e = i*16+k, 256 thr),
// dual accumulator chains for ILP.
__device__ __forceinline__ void mm16(const float2* A, const float2* Bm,
                                     float2* C, int e) {
    int i = e >> 4, k = e & 15;
    float xr0 = 0.f, xi0 = 0.f, xr1 = 0.f, xi1 = 0.f;
#pragma unroll
    for (int j = 0; j < 16; j += 2) {
        float2 a0 = A[(i << 4) + j],     b0 = Bm[(j << 4) + k];
        float2 a1 = A[(i << 4) + j + 1], b1 = Bm[((j + 1) << 4) + k];
        cfma(xr0, xi0, a0.x, a0.y, b0.x, b0.y);
        cfma(xr1, xi1, a1.x, a1.y, b1.x, b1.y);
    }
    C[e] = make_float2(xr0 + xr1, xi0 + xi1);
}

// ---------------------------------------------------------------------------
// k_nop: profiling alignment (ncu -s 5 -c 1 lands on k_main).
// ---------------------------------------------------------------------------
__global__ void k_nop() {}

// ---------------------------------------------------------------------------
// k0_pack: warp W packs samples [32W, 32W+32); packed bit (63-t) = x_t.
// unroll 4 -> 4 load-pairs in flight per ballot chain step.
// Launch: 512 blocks x 256 threads (4096 warps x 32 samples = 131072).
// ---------------------------------------------------------------------------
__global__ void k0_pack(const int* __restrict__ x, int N) {
    int W = (blockIdx.x * blockDim.x + threadIdx.x) >> 5;
    int lane = threadIdx.x & 31;
    int s0 = W << 5;
    if (s0 >= N) return;
    ull mine = 0;
#pragma unroll 4
    for (int q = 0; q < 32; q++) {
        size_t base = (size_t)(s0 + q) << 6;
        unsigned b0 = __ballot_sync(0xFFFFFFFFu, x[base + lane] & 1);
        unsigned b1 = __ballot_sync(0xFFFFFFFFu, x[base + 32 + lane] & 1);
        ull packed = ((ull)__brev(b0) << 32) | (ull)__brev(b1);
        if (lane == q) mine = packed;
    }
    g_xpack[s0 + lane] = mine;
}

// ---------------------------------------------------------------------------
// kA: 64 blocks x 256 threads. Block c builds Seg6[c] from raw B matrices
// (5 smem matmuls), plus Lv2/Rv2 (redundant, tiny) -> Lv8 / Rv8 slices.
// ---------------------------------------------------------------------------
__global__ void kA(const float* __restrict__ br_, const float* __restrict__ bi_,
                   const float* __restrict__ lr_, const float* __restrict__ li_,
                   const float* __restrict__ rr_, const float* __restrict__ ri_) {
    __shared__ float2 sB[512], sT[256], sA3[256], sB3[256], sS6[256];
    __shared__ float2 sLv2[64], sRv2[64];
    __shared__ float sLr[32], sLi[32], sRr[32], sRi[32];
    int e = threadIdx.x, c = blockIdx.x;

    sB[e]       = make_float2(br_[e],       bi_[e]);
    sB[e + 256] = make_float2(br_[e + 256], bi_[e + 256]);
    if (e < 32) { sLr[e] = lr_[e]; sLi[e] = li_[e]; sRr[e] = rr_[e]; sRi[e] = ri_[e]; }
    __syncthreads();

    int a = c >> 3, b = c & 7;
    mm16(sB + (((a >> 1) & 1) << 8), sB + ((a & 1) << 8), sT, e);  __syncthreads();
    mm16(sB + ((a >> 2) << 8), sT, sA3, e);                        __syncthreads();
    mm16(sB + (((b >> 1) & 1) << 8), sB + ((b & 1) << 8), sT, e);  __syncthreads();
    mm16(sB + ((b >> 2) << 8), sT, sB3, e);                        __syncthreads();
    mm16(sA3, sB3, sS6, e);                                        __syncthreads();

    g_seg[(c << 8) + e] = sS6[e];

    if (e < 64) {  // Lv2[(s<<1)|bb][k] = sum_j left[s][j] * B[bb][j][k]
        int v = e >> 4, k = e & 15, s = v >> 1, bb = v & 1;
        float xr = 0.f, xi = 0.f;
#pragma unroll
        for (int j = 0; j < 16; j++) {
            float2 m = sB[(bb << 8) + (j << 4) + k];
            cfma(xr, xi, sLr[s * 16 + j], sLi[s * 16 + j], m.x, m.y);
        }
        sLv2[e] = make_float2(xr, xi);
    } else if (e < 128) {  // Rv2[(bb<<1)|r][i] = sum_j B[bb][i][j] * right[r][j]
        int t2 = e - 64, v = t2 >> 4, i = t2 & 15, bb = v >> 1, r = v & 1;
        float xr = 0.f, xi = 0.f;
#pragma unroll
        for (int j = 0; j < 16; j++) {
            float2 m = sB[(bb << 8) + (i << 4) + j];
            cfma(xr, xi, m.x, m.y, sRr[r * 16 + j], sRi[r * 16 + j]);
        }
        sRv2[t2] = make_float2(xr, xi);
    }
    __syncthreads();

    if (e < 64) {  // Lv8[(a2<<6)|c][k] = sum_j Lv2[a2][j] * Seg6[c][j][k]
        int a2 = e >> 4, k = e & 15;
        float xr = 0.f, xi = 0.f;
#pragma unroll
        for (int j = 0; j < 16; j++) {
            float2 o = sLv2[(a2 << 4) + j];
            float2 m = sS6[(j << 4) + k];
            cfma(xr, xi, o.x, o.y, m.x, m.y);
        }
        g_lv8[(((a2 << 6) | c) << 4) + k] = make_float2(xr, xi);
    } else if (e < 128) {  // Rv8[(c<<2)|b2][i] = sum_j Seg6[c][i][j] * Rv2[b2][j]
        int t2 = e - 64, b2 = t2 >> 4, i = t2 & 15;
        float xr = 0.f, xi = 0.f;
#pragma unroll
        for (int j = 0; j < 16; j++) {
            float2 m = sS6[(i << 4) + j];
            float2 w = sRv2[(b2 << 4) + j];
            cfma(xr, xi, m.x, m.y, w.x, w.y);
        }
        g_rv8[(((c << 2) | b2) << 4) + i] = make_float2(xr, xi);
    }
}

// ---------------------------------------------------------------------------
// kB: 128 blocks x 256 threads. Table expansion with dual-acc ILP.
// Blocks 0..63:  Lvec[(a8<<6)|c] = Lv8[a8].Seg6[c]
// Blocks 64..127: Rvec[(c<<8)|b8] = Seg6[c].Rv8[b8]
// ---------------------------------------------------------------------------
__global__ void kB() {
    __shared__ float2 S[256];
    int blk = blockIdx.x;
    int t = threadIdx.x;

    if (blk < 64) {
        int c = blk;
        S[t] = g_seg[(c << 8) + t];           // S[j*16+k] = Seg6[c][j][k]
        __syncthreads();
        int k = t & 15, a8l = t >> 4;
#pragma unroll 1
        for (int p = 0; p < 16; p++) {
            int a8 = (p << 4) | a8l;
            const float2* w = g_lv8 + (a8 << 4);
            float xr0 = 0.f, xi0 = 0.f, xr1 = 0.f, xi1 = 0.f;
#pragma unroll
            for (int j = 0; j < 16; j += 2) {
                float2 o0 = __ldg(&w[j]),     b0 = S[(j << 4) + k];
                float2 o1 = __ldg(&w[j + 1]), b1 = S[((j + 1) << 4) + k];
                cfma(xr0, xi0, o0.x, o0.y, b0.x, b0.y);
                cfma(xr1, xi1, o1.x, o1.y, b1.x, b1.y);
            }
            g_lvec[(((a8 << 6) | c) << 4) + k] = make_float2(xr0 + xr1, xi0 + xi1);
        }
    } else {
        int c = blk - 64;
        {
            int i = t >> 4, j = t & 15;
            S[(j << 4) | i] = g_seg[(c << 8) + t];  // transposed stage
        }
        __syncthreads();
        int il = t & 15, b8l = t >> 4;
#pragma unroll 1
        for (int p = 0; p < 16; p++) {
            int b8 = (p << 4) | b8l;
            const float2* w = g_rv8 + (b8 << 4);
            float xr0 = 0.f, xi0 = 0.f, xr1 = 0.f, xi1 = 0.f;
#pragma unroll
            for (int j = 0; j < 16; j += 2) {
                float2 w0 = __ldg(&w[j]),     b0 = S[(j << 4) + il];
                float2 w1 = __ldg(&w[j + 1]), b1 = S[((j + 1) << 4) + il];
                cfma(xr0, xi0, b0.x, b0.y, w0.x, w0.y);
                cfma(xr1, xi1, b1.x, b1.y, w1.x, w1.y);
            }
            g_rvec[(((c << 8) | b8) << 4) + il] = make_float2(xr0 + xr1, xi0 + xi1);
        }
    }
}

// ---------------------------------------------------------------------------
// Main kernel (R5-proven). One thread per sample, balanced contiguous chunk
// per block. Table (128 KB) in smem, plain layout; column pairs read in
// lane-rotated order (deterministic 4-phase LDS.128). Register pair u of
// the state holds logical pair (u+rot)&7 after the first matvec.
// ---------------------------------------------------------------------------
__global__ __launch_bounds__(512) void k_main(float* __restrict__ out, int N) {
    extern __shared__ float2 sSeg[];  // 64 * 256 float2 = 128 KB

    {
        const float4* src = reinterpret_cast<const float4*>(g_seg);
        float4* dst = reinterpret_cast<float4*>(sSeg);
        for (int e = threadIdx.x; e < 64 * 128; e += blockDim.x) dst[e] = src[e];
    }
    __syncthreads();

    unsigned sb;
    asm("{ .reg .u64 t; cvta.to.shared.u64 t, %1; cvt.u32.u64 %0, t; }"
        : "=r"(sb) : "l"(sSeg));
    const unsigned rot    = threadIdx.x & 7u;
    const unsigned rot16  = rot << 4;
    const unsigned rot256 = rot << 8;

    int chunk = (N + gridDim.x - 1) / gridDim.x;
    int start = blockIdx.x * chunk;
    int end = min(start + chunk, N);

    for (int s = start + (int)threadIdx.x; s < end; s += (int)blockDim.x) {
        ull packed = __ldg(&g_xpack[s]);
        unsigned idxl = (unsigned)(packed >> 50);         // x0..x13
        unsigned idxr = (unsigned)packed & 0x3FFFu;       // x50..x63
        ull sp = packed << 14;                            // x14 at bit 63

        // ---- start vector: Lvec[idxl], logical register order ----
        float mr[16], mi[16];
        {
            const char* lb = (const char*)g_lvec + ((size_t)idxl << 7);
#pragma unroll
            for (int u = 0; u < 8; u++) {
                ull a, b;
                ldg128(lb + (u << 4), a, b);
                unpack2(a, mr[2 * u],     mi[2 * u]);
                unpack2(b, mr[2 * u + 1], mi[2 * u + 1]);
            }
        }

        // ---- matvec 1: rows addressed by immediate offsets ----
        {
            unsigned idx = (unsigned)(sp >> 58);
            sp <<= 6;
            unsigned mb = sb + (idx << 11);
            ull P[16], Q[16];
#pragma unroll
            for (int e = 0; e < 16; e++) { P[e] = 0ull; Q[e] = 0ull; }
            unsigned pu[8];
#pragma unroll
            for (int u = 0; u < 8; u++) pu[u] = mb + ((rot16 + (u << 4)) & 127u);
#pragma unroll
            for (int i = 0; i < 16; i++) {
                float ar = mr[i], ai = mi[i];
                ull arr = pack2(ar, ar), ai2 = pack2(ai, -ai);
#pragma unroll
                for (int u = 0; u < 8; u++) {
                    ull b0, b1;
                    lds128(pu[u] + (unsigned)(i << 7), b0, b1);
                    P[2 * u]     = ffma2(arr, b0, P[2 * u]);
                    Q[2 * u]     = ffma2(ai2, b0, Q[2 * u]);
                    P[2 * u + 1] = ffma2(arr, b1, P[2 * u + 1]);
                    Q[2 * u + 1] = ffma2(ai2, b1, Q[2 * u + 1]);
                }
            }
#pragma unroll
            for (int e = 0; e < 16; e++) {
                float pl, ph, ql, qh;
                unpack2(P[e], pl, ph);
                unpack2(Q[e], ql, qh);
                mr[e] = pl + qh;   // nr = ar*bx - ai*by
                mi[e] = ph + ql;   // ni = ar*by + ai*bx
            }
        }

        // ---- matvecs 2..6: state pair u holds logical pair (u+rot)&7 ----
#pragma unroll 1
        for (int kseg = 1; kseg < 6; kseg++) {
            unsigned idx = (unsigned)(sp >> 58);
            sp <<= 6;
            unsigned mb = sb + (idx << 11);
            ull P[16], Q[16];
#pragma unroll
            for (int e = 0; e < 16; e++) { P[e] = 0ull; Q[e] = 0ull; }
            unsigned pu[8];
#pragma unroll
            for (int u = 0; u < 8; u++) pu[u] = mb + ((rot16 + (u << 4)) & 127u);
#pragma unroll
            for (int spn = 0; spn < 8; spn++) {
                unsigned row = (rot256 + (unsigned)(spn << 8)) & 2047u;
#pragma unroll
                for (int hf = 0; hf < 2; hf++) {
                    float ar = mr[2 * spn + hf], ai = mi[2 * spn + hf];
                    ull arr = pack2(ar, ar), ai2 = pack2(ai, -ai);
#pragma unroll
                    for (int u = 0; u < 8; u++) {
                        ull b0, b1;
                        lds128(pu[u] + row + (unsigned)(hf << 7), b0, b1);
                        P[2 * u]     = ffma2(arr, b0, P[2 * u]);
                        Q[2 * u]     = ffma2(ai2, b0, Q[2 * u]);
                        P[2 * u + 1] = ffma2(arr, b1, P[2 * u + 1]);
                        Q[2 * u + 1] = ffma2(ai2, b1, Q[2 * u + 1]);
                    }
                }
            }
#pragma unroll
            for (int e = 0; e < 16; e++) {
                float pl, ph, ql, qh;
                unpack2(P[e], pl, ph);
                unpack2(Q[e], ql, qh);
                mr[e] = pl + qh;
                mi[e] = ph + ql;
            }
        }

        // ---- final dot with Rvec[idxr], same pair rotation ----
        float accr = 0.f, acci = 0.f;
        {
            const char* rb = (const char*)g_rvec + ((size_t)idxr << 7);
#pragma unroll
            for (int u = 0; u < 8; u++) {
                ull a, b;
                ldg128(rb + ((rot16 + (u << 4)) & 127u), a, b);
                float c0x, c0y, c1x, c1y;
                unpack2(a, c0x, c0y);
                unpack2(b, c1x, c1y);
                int e0 = 2 * u, e1 = 2 * u + 1;
                accr = fmaf(mr[e0], c0x, accr);  accr = fmaf(-mi[e0], c0y, accr);
                acci = fmaf(mr[e0], c0y, acci);  acci = fmaf(mi[e0], c0x, acci);
                accr = fmaf(mr[e1], c1x, accr);  accr = fmaf(-mi[e1], c1y, accr);
                acci = fmaf(mr[e1], c1y, acci);  acci = fmaf(mi[e1], c1x, acci);
            }
        }

        out[s]     = accr;
        out[N + s] = acci;
    }
}

// ---------------------------------------------------------------------------
// kernel_launch
// inputs (metadata order): x, left_r, left_i, bulk_r, bulk_i, right_r, right_i
// out: float32, [2, N] flattened (re then im)
// Launch pattern [nop, nop, k0, kA, kB, k_main] puts k_main at global launch
// index 5, so ncu (-s 5 -c 1) profiles the hot kernel.
// ---------------------------------------------------------------------------
extern "C" void kernel_launch(void* const* d_in, const int* in_sizes, int n_in,
                              void* d_out, int out_size) {
    const int*   x       = (const int*)d_in[0];
    const float* left_r  = (const float*)d_in[1];
    const float* left_i  = (const float*)d_in[2];
    const float* bulk_r  = (const float*)d_in[3];
    const float* bulk_i  = (const float*)d_in[4];
    const float* right_r = (const float*)d_in[5];
    const float* right_i = (const float*)d_in[6];
    float* out = (float*)d_out;

    int N = in_sizes[0] / 64;

    static const size_t kSmem = 64 * 256 * sizeof(float2);  // 128 KB
    cudaFuncSetAttribute(k_main, cudaFuncAttributeMaxDynamicSharedMemorySize,
                         (int)kSmem);

    k_nop<<<1, 32>>>();
    k_nop<<<1, 32>>>();
    k0_pack<<<(131072 + 255) / 256, 256>>>(x, N);
    kA<<<64, 256>>>(bulk_r, bulk_i, left_r, left_i, right_r, right_i);
    kB<<<128, 256>>>();
    k_main<<<148, 512, kSmem>>>(out, N);
}

// round 9
// speedup vs baseline: 1.2882x; 1.0496x over previous
#include <cuda_runtime.h>
#include <cstdint>

// ---------------------------------------------------------------------------
// MPS amplitude contraction, segment-table approach (v9).
// amplitude(s) = left[x0] . B[x1] ... B[x62] . right[x63]   (complex, D=16)
//
// Split: Lvec covers x0..x13 (14 bits), 6 x Seg6 cover x14..x49 (36 bits),
//        Rvec covers x50..x63 (14 bits).
// v9: warp-cooperative staged Lvec/Rvec gathers (32 lines/warp-iter instead
//     of 512 L1 wavefronts), kA parallel trees (512 thr), launch order puts
//     k_main at index 3 where ncu (-s 5, 2 harness launches) samples.
// ---------------------------------------------------------------------------

typedef unsigned long long ull;

__device__ float2 g_seg [64 * 256];
__device__ float2 g_lv8 [256 * 16];
__device__ float2 g_rv8 [256 * 16];
__device__ float2 g_lvec[16384 * 16];
__device__ float2 g_rvec[16384 * 16];
__device__ ull    g_xpack[131072];

// ---- packed fp32x2 helpers ----
__device__ __forceinline__ ull pack2(float lo, float hi) {
    ull r; asm("mov.b64 %0, {%1,%2};" : "=l"(r) : "f"(lo), "f"(hi)); return r;
}
__device__ __forceinline__ void unpack2(ull v, float& lo, float& hi) {
    asm("mov.b64 {%0,%1}, %2;" : "=f"(lo), "=f"(hi) : "l"(v));
}
__device__ __forceinline__ ull ffma2(ull a, ull b, ull c) {
    ull d; asm("fma.rn.f32x2 %0, %1, %2, %3;" : "=l"(d) : "l"(a), "l"(b), "l"(c));
    return d;
}
__device__ __forceinline__ void lds128(unsigned addr, ull& p0, ull& p1) {
    asm volatile("ld.shared.v2.b64 {%0,%1}, [%2];" : "=l"(p0), "=l"(p1) : "r"(addr));
}
__device__ __forceinline__ void sts128(unsigned addr, ull p0, ull p1) {
    asm volatile("st.shared.v2.b64 [%0], {%1,%2};" :: "r"(addr), "l"(p0), "l"(p1));
}
__device__ __forceinline__ void ldg128(const void* p, ull& p0, ull& p1) {
    asm volatile("ld.global.nc.v2.b64 {%0,%1}, [%2];" : "=l"(p0), "=l"(p1) : "l"(p));
}

// scalar complex fma: (rr,ri) += (ax+i ay) * (bx+i by)
__device__ __forceinline__ void cfma(float& rr, float& ri, float ax, float ay,
                                     float bx, float by) {
    rr = fmaf(ax, bx, rr);
    rr = fmaf(-ay, by, rr);
    ri = fmaf(ax, by, ri);
    ri = fmaf(ay, bx, ri);
}

// 16x16 complex matmul, one output element per thread (e = i*16+k, 256 thr),
// dual accumulator chains for ILP.
__device__ __forceinline__ void mm16(const float2* A, const float2* Bm,
                                     float2* C, int e) {
    int i = e >> 4, k = e & 15;
    float xr0 = 0.f, xi0 = 0.f, xr1 = 0.f, xi1 = 0.f;
#pragma unroll
    for (int j = 0; j < 16; j += 2) {
        float2 a0 = A[(i << 4) + j],     b0 = Bm[(j << 4) + k];
        float2 a1 = A[(i << 4) + j + 1], b1 = Bm[((j + 1) << 4) + k];
        cfma(xr0, xi0, a0.x, a0.y, b0.x, b0.y);
        cfma(xr1, xi1, a1.x, a1.y, b1.x, b1.y);
    }
    C[e] = make_float2(xr0 + xr1, xi0 + xi1);
}

// ---------------------------------------------------------------------------
// k0_pack: warp W packs samples [32W, 32W+32); packed bit (63-t) = x_t.
// ---------------------------------------------------------------------------
__global__ void k0_pack(const int* __restrict__ x, int N) {
    int W = (blockIdx.x * blockDim.x + threadIdx.x) >> 5;
    int lane = threadIdx.x & 31;
    int s0 = W << 5;
    if (s0 >= N) return;
    ull mine = 0;
#pragma unroll 4
    for (int q = 0; q < 32; q++) {
        size_t base = (size_t)(s0 + q) << 6;
        unsigned b0 = __ballot_sync(0xFFFFFFFFu, x[base + lane] & 1);
        unsigned b1 = __ballot_sync(0xFFFFFFFFu, x[base + 32 + lane] & 1);
        ull packed = ((ull)__brev(b0) << 32) | (ull)__brev(b1);
        if (lane == q) mine = packed;
    }
    g_xpack[s0 + lane] = mine;
}

// ---------------------------------------------------------------------------
// kA: 64 blocks x 512 threads. Block c builds Seg6[c]; the two Seg3 trees
// (a = c>>3, b = c&7) run in parallel on thread-halves (3 matmul rounds).
// Also emits Lv2/Rv2 -> Lv8/Rv8 slices.
// ---------------------------------------------------------------------------
__global__ __launch_bounds__(512) void kA(
        const float* __restrict__ br_, const float* __restrict__ bi_,
        const float* __restrict__ lr_, const float* __restrict__ li_,
        const float* __restrict__ rr_, const float* __restrict__ ri_) {
    __shared__ float2 sB[512], sT[2][256], sP[2][256], sS6[256];
    __shared__ float2 sLv2[64], sRv2[64];
    __shared__ float sLr[32], sLi[32], sRr[32], sRi[32];
    int e = threadIdx.x, c = blockIdx.x;
    int half = e >> 8, e2 = e & 255;

    sB[e] = make_float2(br_[e], bi_[e]);
    if (e < 32) { sLr[e] = lr_[e]; sLi[e] = li_[e]; sRr[e] = rr_[e]; sRi[e] = ri_[e]; }
    __syncthreads();

    int a = c >> 3, b = c & 7;
    int v = half ? b : a;
    mm16(sB + (((v >> 1) & 1) << 8), sB + ((v & 1) << 8), sT[half], e2);
    __syncthreads();
    mm16(sB + ((v >> 2) << 8), sT[half], sP[half], e2);
    __syncthreads();
    if (half == 0) mm16(sP[0], sP[1], sS6, e2);     // Seg6[c] = Seg3[a].Seg3[b]
    __syncthreads();

    if (half == 0) g_seg[(c << 8) + e2] = sS6[e2];

    if (e < 64) {  // Lv2[(s<<1)|bb][k] = sum_j left[s][j] * B[bb][j][k]
        int vv = e >> 4, k = e & 15, s = vv >> 1, bb = vv & 1;
        float xr = 0.f, xi = 0.f;
#pragma unroll
        for (int j = 0; j < 16; j++) {
            float2 m = sB[(bb << 8) + (j << 4) + k];
            cfma(xr, xi, sLr[s * 16 + j], sLi[s * 16 + j], m.x, m.y);
        }
        sLv2[e] = make_float2(xr, xi);
    } else if (e < 128) {  // Rv2[(bb<<1)|r][i] = sum_j B[bb][i][j] * right[r][j]
        int t2 = e - 64, vv = t2 >> 4, i = t2 & 15, bb = vv >> 1, r = vv & 1;
        float xr = 0.f, xi = 0.f;
#pragma unroll
        for (int j = 0; j < 16; j++) {
            float2 m = sB[(bb << 8) + (i << 4) + j];
            cfma(xr, xi, m.x, m.y, sRr[r * 16 + j], sRi[r * 16 + j]);
        }
        sRv2[t2] = make_float2(xr, xi);
    }
    __syncthreads();

    if (e < 64) {  // Lv8[(a2<<6)|c][k] = sum_j Lv2[a2][j] * Seg6[c][j][k]
        int a2 = e >> 4, k = e & 15;
        float xr = 0.f, xi = 0.f;
#pragma unroll
        for (int j = 0; j < 16; j++) {
            float2 o = sLv2[(a2 << 4) + j];
            float2 m = sS6[(j << 4) + k];
            cfma(xr, xi, o.x, o.y, m.x, m.y);
        }
        g_lv8[(((a2 << 6) | c) << 4) + k] = make_float2(xr, xi);
    } else if (e < 128) {  // Rv8[(c<<2)|b2][i] = sum_j Seg6[c][i][j] * Rv2[b2][j]
        int t2 = e - 64, b2 = t2 >> 4, i = t2 & 15;
        float xr = 0.f, xi = 0.f;
#pragma unroll
        for (int j = 0; j < 16; j++) {
            float2 m = sS6[(i << 4) + j];
            float2 w = sRv2[(b2 << 4) + j];
            cfma(xr, xi, m.x, m.y, w.x, w.y);
        }
        g_rv8[(((c << 2) | b2) << 4) + i] = make_float2(xr, xi);
    }
}

// ---------------------------------------------------------------------------
// kB: 128 blocks x 256 threads. Table expansion with dual-acc ILP.
// Blocks 0..63:  Lvec[(a8<<6)|c] = Lv8[a8].Seg6[c]
// Blocks 64..127: Rvec[(c<<8)|b8] = Seg6[c].Rv8[b8]
// ---------------------------------------------------------------------------
__global__ void kB() {
    __shared__ float2 S[256];
    int blk = blockIdx.x;
    int t = threadIdx.x;

    if (blk < 64) {
        int c = blk;
        S[t] = g_seg[(c << 8) + t];           // S[j*16+k] = Seg6[c][j][k]
        __syncthreads();
        int k = t & 15, a8l = t >> 4;
#pragma unroll 1
        for (int p = 0; p < 16; p++) {
            int a8 = (p << 4) | a8l;
            const float2* w = g_lv8 + (a8 << 4);
            float xr0 = 0.f, xi0 = 0.f, xr1 = 0.f, xi1 = 0.f;
#pragma unroll
            for (int j = 0; j < 16; j += 2) {
                float2 o0 = __ldg(&w[j]),     b0 = S[(j << 4) + k];
                float2 o1 = __ldg(&w[j + 1]), b1 = S[((j + 1) << 4) + k];
                cfma(xr0, xi0, o0.x, o0.y, b0.x, b0.y);
                cfma(xr1, xi1, o1.x, o1.y, b1.x, b1.y);
            }
            g_lvec[(((a8 << 6) | c) << 4) + k] = make_float2(xr0 + xr1, xi0 + xi1);
        }
    } else {
        int c = blk - 64;
        {
            int i = t >> 4, j = t & 15;
            S[(j << 4) | i] = g_seg[(c << 8) + t];  // transposed stage
        }
        __syncthreads();
        int il = t & 15, b8l = t >> 4;
#pragma unroll 1
        for (int p = 0; p < 16; p++) {
            int b8 = (p << 4) | b8l;
            const float2* w = g_rv8 + (b8 << 4);
            float xr0 = 0.f, xi0 = 0.f, xr1 = 0.f, xi1 = 0.f;
#pragma unroll
            for (int j = 0; j < 16; j += 2) {
                float2 w0 = __ldg(&w[j]),     b0 = S[(j << 4) + il];
                float2 w1 = __ldg(&w[j + 1]), b1 = S[((j + 1) << 4) + il];
                cfma(xr0, xi0, b0.x, b0.y, w0.x, w0.y);
                cfma(xr1, xi1, b1.x, b1.y, w1.x, w1.y);
            }
            g_rvec[(((c << 8) | b8) << 4) + il] = make_float2(xr0 + xr1, xi0 + xi1);
        }
    }
}

// ---------------------------------------------------------------------------
// Main kernel. One thread per sample, balanced contiguous chunk per block,
// warp-uniform outer loop. Smem: 128 KB Seg6 table + 64 KB gather staging.
// Lvec/Rvec fetched warp-cooperatively: 8 lanes pull one sample's 128B line
// (idx via shuffle), staged in the owner's private 128B region, read back
// with the rotation the matvec pipeline expects. Table column pairs read in
// lane-rotated order (deterministic 4-phase LDS.128). Register pair u of
// the state holds logical pair (u+rot)&7 after the first matvec.
// ---------------------------------------------------------------------------
__global__ __launch_bounds__(512) void k_main(float* __restrict__ out, int N) {
    extern __shared__ float2 smem_all[];
    float2* sSeg = smem_all;                    // 16384 float2 = 128 KB

    {
        const float4* src = reinterpret_cast<const float4*>(g_seg);
        float4* dst = reinterpret_cast<float4*>(sSeg);
        for (int e = threadIdx.x; e < 64 * 128; e += blockDim.x) dst[e] = src[e];
    }
    __syncthreads();

    unsigned sb;
    asm("{ .reg .u64 t; cvta.to.shared.u64 t, %1; cvt.u32.u64 %0, t; }"
        : "=r"(sb) : "l"(smem_all));
    const unsigned stgb   = sb + 131072u;            // staging base (bytes)
    const unsigned lane   = threadIdx.x & 31u;
    const unsigned rot    = threadIdx.x & 7u;
    const unsigned rot16  = rot << 4;
    const unsigned rot256 = rot << 8;
    const unsigned myStg  = stgb + ((unsigned)threadIdx.x << 7);
    const unsigned warpStg = stgb + ((unsigned)(threadIdx.x & ~31u) << 7);
    const int sub    = (int)(lane >> 3);             // 0..3
    const int chunku = (int)(lane & 7);              // 16B chunk this lane moves

    int chunk = (N + gridDim.x - 1) / gridDim.x;
    int start = blockIdx.x * chunk;
    int end = min(start + chunk, N);

    for (int base = start + (int)((threadIdx.x >> 5) << 5); base < end;
         base += (int)blockDim.x) {
        int s = base + (int)lane;
        bool active = s < end;
        ull packed = active ? __ldg(&g_xpack[s]) : 0ull;
        unsigned idxl = (unsigned)(packed >> 50);         // x0..x13
        unsigned idxr = (unsigned)packed & 0x3FFFu;       // x50..x63
        ull sp = packed << 14;                            // x14 at bit 63

        // ---- staged Lvec gather (slots swizzled by owner&7) ----
#pragma unroll
        for (int g = 0; g < 8; g++) {
            int owner = (g << 2) + sub;
            unsigned oidx = __shfl_sync(0xFFFFFFFFu, idxl, owner);
            const char* p = (const char*)g_lvec + ((size_t)oidx << 7) + (chunku << 4);
            ull a, b; ldg128(p, a, b);
            unsigned slot = (unsigned)(chunku ^ (owner & 7));
            sts128(warpStg + ((unsigned)owner << 7) + (slot << 4), a, b);
        }
        __syncwarp();

        float mr[16], mi[16];
#pragma unroll
        for (int u = 0; u < 8; u++) {                    // logical order
            unsigned slot = (unsigned)u ^ rot;
            ull a, b; lds128(myStg + (slot << 4), a, b);
            unpack2(a, mr[2 * u],     mi[2 * u]);
            unpack2(b, mr[2 * u + 1], mi[2 * u + 1]);
        }
        __syncwarp();   // all reads done before staging is reused below

        // ---- matvec 1: m in logical order, rows by immediate offsets ----
        {
            unsigned idx = (unsigned)(sp >> 58);
            sp <<= 6;
            unsigned mb = sb + (idx << 11);
            ull P[16], Q[16];
#pragma unroll
            for (int e = 0; e < 16; e++) { P[e] = 0ull; Q[e] = 0ull; }
            unsigned pu[8];
#pragma unroll
            for (int u = 0; u < 8; u++) pu[u] = mb + ((rot16 + (u << 4)) & 127u);
#pragma unroll
            for (int i = 0; i < 16; i++) {
                float ar = mr[i], ai = mi[i];
                ull arr = pack2(ar, ar), ai2 = pack2(ai, -ai);
#pragma unroll
                for (int u = 0; u < 8; u++) {
                    ull b0, b1;
                    lds128(pu[u] + (unsigned)(i << 7), b0, b1);
                    P[2 * u]     = ffma2(arr, b0, P[2 * u]);
                    Q[2 * u]     = ffma2(ai2, b0, Q[2 * u]);
                    P[2 * u + 1] = ffma2(arr, b1, P[2 * u + 1]);
                    Q[2 * u + 1] = ffma2(ai2, b1, Q[2 * u + 1]);
                }
            }
#pragma unroll
            for (int e = 0; e < 16; e++) {
                float pl, ph, ql, qh;
                unpack2(P[e], pl, ph);
                unpack2(Q[e], ql, qh);
                mr[e] = pl + qh;   // nr = ar*bx - ai*by
                mi[e] = ph + ql;   // ni = ar*by + ai*bx
            }
        }

        // ---- matvecs 2..6: state pair u holds logical pair (u+rot)&7 ----
#pragma unroll 1
        for (int kseg = 1; kseg < 6; kseg++) {
            unsigned idx = (unsigned)(sp >> 58);
            sp <<= 6;
            unsigned mb = sb + (idx << 11);
            ull P[16], Q[16];
#pragma unroll
            for (int e = 0; e < 16; e++) { P[e] = 0ull; Q[e] = 0ull; }
            unsigned pu[8];
#pragma unroll
            for (int u = 0; u < 8; u++) pu[u] = mb + ((rot16 + (u << 4)) & 127u);
#pragma unroll
            for (int spn = 0; spn < 8; spn++) {
                unsigned row = (rot256 + (unsigned)(spn << 8)) & 2047u;
#pragma unroll
                for (int hf = 0; hf < 2; hf++) {
                    float ar = mr[2 * spn + hf], ai = mi[2 * spn + hf];
                    ull arr = pack2(ar, ar), ai2 = pack2(ai, -ai);
#pragma unroll
                    for (int u = 0; u < 8; u++) {
                        ull b0, b1;
                        lds128(pu[u] + row + (unsigned)(hf << 7), b0, b1);
                        P[2 * u]     = ffma2(arr, b0, P[2 * u]);
                        Q[2 * u]     = ffma2(ai2, b0, Q[2 * u]);
                        P[2 * u + 1] = ffma2(arr, b1, P[2 * u + 1]);
                        Q[2 * u + 1] = ffma2(ai2, b1, Q[2 * u + 1]);
                    }
                }
            }
#pragma unroll
            for (int e = 0; e < 16; e++) {
                float pl, ph, ql, qh;
                unpack2(P[e], pl, ph);
                unpack2(Q[e], ql, qh);
                mr[e] = pl + qh;
                mi[e] = ph + ql;
            }
        }

        // ---- staged Rvec gather (unswizzled slots; read order is rotated) ----
#pragma unroll
        for (int g = 0; g < 8; g++) {
            int owner = (g << 2) + sub;
            unsigned oidx = __shfl_sync(0xFFFFFFFFu, idxr, owner);
            const char* p = (const char*)g_rvec + ((size_t)oidx << 7) + (chunku << 4);
            ull a, b; ldg128(p, a, b);
            sts128(warpStg + ((unsigned)owner << 7) + ((unsigned)chunku << 4), a, b);
        }
        __syncwarp();

        float accr = 0.f, acci = 0.f;
#pragma unroll
        for (int u = 0; u < 8; u++) {
            unsigned lp = (u + rot) & 7u;               // logical pair at step u
            ull a, b; lds128(myStg + (lp << 4), a, b);
            float c0x, c0y, c1x, c1y;
            unpack2(a, c0x, c0y);
            unpack2(b, c1x, c1y);
            int e0 = 2 * u, e1 = 2 * u + 1;
            accr = fmaf(mr[e0], c0x, accr);  accr = fmaf(-mi[e0], c0y, accr);
            acci = fmaf(mr[e0], c0y, acci);  acci = fmaf(mi[e0], c0x, acci);
            accr = fmaf(mr[e1], c1x, accr);  accr = fmaf(-mi[e1], c1y, accr);
            acci = fmaf(mr[e1], c1y, acci);  acci = fmaf(mi[e1], c1x, acci);
        }
        __syncwarp();   // staging reused next iteration

        if (active) {
            out[s]     = accr;
            out[N + s] = acci;
        }
    }
}

// ---------------------------------------------------------------------------
// kernel_launch
// inputs (metadata order): x, left_r, left_i, bulk_r, bulk_i, right_r, right_i
// out: float32, [2, N] flattened (re then im)
// Order [k0, kA, kB, k_main]: with the harness's 2 internal pre-launches,
// ncu -s 5 lands on k_main.
// ---------------------------------------------------------------------------
extern "C" void kernel_launch(void* const* d_in, const int* in_sizes, int n_in,
                              void* d_out, int out_size) {
    const int*   x       = (const int*)d_in[0];
    const float* left_r  = (const float*)d_in[1];
    const float* left_i  = (const float*)d_in[2];
    const float* bulk_r  = (const float*)d_in[3];
    const float* bulk_i  = (const float*)d_in[4];
    const float* right_r = (const float*)d_in[5];
    const float* right_i = (const float*)d_in[6];
    float* out = (float*)d_out;

    int N = in_sizes[0] / 64;

    static const size_t kSmem = 192 * 1024;  // 128 KB table + 64 KB staging
    cudaFuncSetAttribute(k_main, cudaFuncAttributeMaxDynamicSharedMemorySize,
                         (int)kSmem);

    k0_pack<<<(131072 + 255) / 256, 256>>>(x, N);
    kA<<<64, 512>>>(bulk_r, bulk_i, left_r, left_i, right_r, right_i);
    kB<<<128, 256>>>();
    k_main<<<148, 512, kSmem>>>(out, N);
}